// round 1
// baseline (speedup 1.0000x reference)
#include <cuda_runtime.h>
#include <cuda_bf16.h>
#include <math.h>

// Problem constants
#define BB 8
#define TT 2048
#define DD 1024
#define MIN_TEMP 0.1f
#define MAX_TEMP 5.0f
#define EPS_T 1e-8f

// Scratch (no cudaMalloc allowed) — __device__ globals.
__device__ float g_q[BB * TT * DD];        // 64 MB
__device__ float g_k[BB * TT * DD];        // 64 MB
__device__ float g_v[BB * TT * DD];        // 64 MB
__device__ float g_scores[BB * TT * TT];   // 134 MB
__device__ float g_temp[BB * TT];

// ---------------------------------------------------------------------------
// Tiled SGEMM: C[m][n] = sum_k A[m][k] * B'[k][n]
//   NT variant: B stored row-major [N][K] (K-contiguous)  -> C = A * B^T
//   NN variant: B stored row-major [K][N] (N-contiguous)  -> C = A * B
// Tile: 128x128x16, 256 threads, 8x8 per-thread microtile. No bounds checks:
// all dims are multiples of the tile sizes for this problem.
// Optional per-row scale (temp) applied in the epilogue.
// ---------------------------------------------------------------------------
#define BM 128
#define BN 128
#define BK 16
#define SPAD 4   // smem row pad (keeps float4 alignment: (BM+SPAD)%4==0)

__global__ __launch_bounds__(256) void gemm_nt(
    const float* __restrict__ A, const float* __restrict__ B, float* __restrict__ C,
    int M, int N, int K,
    size_t strideA, size_t strideB, size_t strideC,
    const float* __restrict__ temp, int tempStride)
{
    __shared__ float As[BK][BM + SPAD];
    __shared__ float Bs[BK][BN + SPAD];

    const int bz = blockIdx.z;
    A += (size_t)bz * strideA;
    B += (size_t)bz * strideB;
    C += (size_t)bz * strideC;

    const int m0 = blockIdx.y * BM;
    const int n0 = blockIdx.x * BN;
    const int tid = threadIdx.x;
    const int tx = tid & 15;   // 0..15 -> n microtile
    const int ty = tid >> 4;   // 0..15 -> m microtile

    float acc[8][8];
#pragma unroll
    for (int i = 0; i < 8; i++)
#pragma unroll
        for (int j = 0; j < 8; j++) acc[i][j] = 0.0f;

    for (int kb = 0; kb < K; kb += BK) {
        // Load A tile (128 rows x 16 k) and B tile (128 rows x 16 k),
        // both K-contiguous in gmem; store transposed [k][row] in smem.
#pragma unroll
        for (int it = 0; it < 2; it++) {
            int f4  = tid + it * 256;       // 0..511
            int row = f4 >> 2;              // 0..127
            int k4  = (f4 & 3) * 4;         // 0,4,8,12
            float4 va = *(const float4*)(A + (size_t)(m0 + row) * K + kb + k4);
            As[k4 + 0][row] = va.x; As[k4 + 1][row] = va.y;
            As[k4 + 2][row] = va.z; As[k4 + 3][row] = va.w;
            float4 vb = *(const float4*)(B + (size_t)(n0 + row) * K + kb + k4);
            Bs[k4 + 0][row] = vb.x; Bs[k4 + 1][row] = vb.y;
            Bs[k4 + 2][row] = vb.z; Bs[k4 + 3][row] = vb.w;
        }
        __syncthreads();

#pragma unroll
        for (int k = 0; k < BK; k++) {
            float a[8], b[8];
            *(float4*)(a)     = *(const float4*)&As[k][ty * 8];
            *(float4*)(a + 4) = *(const float4*)&As[k][ty * 8 + 4];
            *(float4*)(b)     = *(const float4*)&Bs[k][tx * 8];
            *(float4*)(b + 4) = *(const float4*)&Bs[k][tx * 8 + 4];
#pragma unroll
            for (int i = 0; i < 8; i++)
#pragma unroll
                for (int j = 0; j < 8; j++) acc[i][j] = fmaf(a[i], b[j], acc[i][j]);
        }
        __syncthreads();
    }

#pragma unroll
    for (int i = 0; i < 8; i++) {
        int m = m0 + ty * 8 + i;
        float s = (temp != nullptr) ? temp[bz * tempStride + m] : 1.0f;
        float4 o0 = make_float4(acc[i][0]*s, acc[i][1]*s, acc[i][2]*s, acc[i][3]*s);
        float4 o1 = make_float4(acc[i][4]*s, acc[i][5]*s, acc[i][6]*s, acc[i][7]*s);
        *(float4*)&C[(size_t)m * N + n0 + tx * 8]     = o0;
        *(float4*)&C[(size_t)m * N + n0 + tx * 8 + 4] = o1;
    }
}

__global__ __launch_bounds__(256) void gemm_nn(
    const float* __restrict__ A, const float* __restrict__ B, float* __restrict__ C,
    int M, int N, int K,
    size_t strideA, size_t strideB, size_t strideC)
{
    __shared__ float As[BK][BM + SPAD];
    __shared__ float Bs[BK][BN + SPAD];

    const int bz = blockIdx.z;
    A += (size_t)bz * strideA;
    B += (size_t)bz * strideB;
    C += (size_t)bz * strideC;

    const int m0 = blockIdx.y * BM;
    const int n0 = blockIdx.x * BN;
    const int tid = threadIdx.x;
    const int tx = tid & 15;
    const int ty = tid >> 4;

    float acc[8][8];
#pragma unroll
    for (int i = 0; i < 8; i++)
#pragma unroll
        for (int j = 0; j < 8; j++) acc[i][j] = 0.0f;

    for (int kb = 0; kb < K; kb += BK) {
#pragma unroll
        for (int it = 0; it < 2; it++) {
            int f4  = tid + it * 256;
            // A: K-contiguous, transpose into smem
            int row = f4 >> 2;
            int k4  = (f4 & 3) * 4;
            float4 va = *(const float4*)(A + (size_t)(m0 + row) * K + kb + k4);
            As[k4 + 0][row] = va.x; As[k4 + 1][row] = va.y;
            As[k4 + 2][row] = va.z; As[k4 + 3][row] = va.w;
            // B: N-contiguous (ldb == N), copy rows straight in
            int krow = f4 >> 5;            // 0..15
            int n4   = (f4 & 31) * 4;      // 0..124
            float4 vb = *(const float4*)(B + (size_t)(kb + krow) * N + n0 + n4);
            *(float4*)&Bs[krow][n4] = vb;
        }
        __syncthreads();

#pragma unroll
        for (int k = 0; k < BK; k++) {
            float a[8], b[8];
            *(float4*)(a)     = *(const float4*)&As[k][ty * 8];
            *(float4*)(a + 4) = *(const float4*)&As[k][ty * 8 + 4];
            *(float4*)(b)     = *(const float4*)&Bs[k][tx * 8];
            *(float4*)(b + 4) = *(const float4*)&Bs[k][tx * 8 + 4];
#pragma unroll
            for (int i = 0; i < 8; i++)
#pragma unroll
                for (int j = 0; j < 8; j++) acc[i][j] = fmaf(a[i], b[j], acc[i][j]);
        }
        __syncthreads();
    }

#pragma unroll
    for (int i = 0; i < 8; i++) {
        int m = m0 + ty * 8 + i;
        *(float4*)&C[(size_t)m * N + n0 + tx * 8] =
            make_float4(acc[i][0], acc[i][1], acc[i][2], acc[i][3]);
        *(float4*)&C[(size_t)m * N + n0 + tx * 8 + 4] =
            make_float4(acc[i][4], acc[i][5], acc[i][6], acc[i][7]);
    }
}

// ---------------------------------------------------------------------------
// Per-query temperature: temp = clip(hbar / (||q|| + eps), 0.1, 5.0)
// One block (128 threads) per row of q (16384 rows x 1024).
// ---------------------------------------------------------------------------
__global__ __launch_bounds__(128) void qnorm_temp(
    const float* __restrict__ q, const float* __restrict__ hbar,
    float* __restrict__ temp)
{
    const int row = blockIdx.x;
    const float* qr = q + (size_t)row * DD;
    float s = 0.0f;
    for (int i = threadIdx.x; i < DD; i += 128) {
        float v = qr[i];
        s = fmaf(v, v, s);
    }
#pragma unroll
    for (int off = 16; off > 0; off >>= 1)
        s += __shfl_xor_sync(0xFFFFFFFFu, s, off);
    __shared__ float ws[4];
    int lane = threadIdx.x & 31, wid = threadIdx.x >> 5;
    if (lane == 0) ws[wid] = s;
    __syncthreads();
    if (threadIdx.x == 0) {
        float tot = ws[0] + ws[1] + ws[2] + ws[3];
        float t = hbar[0] / (sqrtf(tot) + EPS_T);
        t = fminf(fmaxf(t, MIN_TEMP), MAX_TEMP);
        temp[row] = t;
    }
}

// ---------------------------------------------------------------------------
// In-place row softmax over rows of length 2048. One block (256 threads) per
// row; 8 elements/thread kept in registers — one gmem read, one gmem write.
// ---------------------------------------------------------------------------
__global__ __launch_bounds__(256) void softmax_rows(float* __restrict__ s)
{
    float* p = s + (size_t)blockIdx.x * TT;
    const int tid = threadIdx.x;
    float v[8];
#pragma unroll
    for (int i = 0; i < 8; i++) v[i] = p[tid + i * 256];

    __shared__ float red[8];
    const int lane = tid & 31, wid = tid >> 5;

    // max
    float m = v[0];
#pragma unroll
    for (int i = 1; i < 8; i++) m = fmaxf(m, v[i]);
#pragma unroll
    for (int off = 16; off > 0; off >>= 1)
        m = fmaxf(m, __shfl_xor_sync(0xFFFFFFFFu, m, off));
    if (lane == 0) red[wid] = m;
    __syncthreads();
    m = red[0];
#pragma unroll
    for (int w = 1; w < 8; w++) m = fmaxf(m, red[w]);
    __syncthreads();

    // sum of exp
    float sum = 0.0f;
#pragma unroll
    for (int i = 0; i < 8; i++) {
        v[i] = expf(v[i] - m);
        sum += v[i];
    }
#pragma unroll
    for (int off = 16; off > 0; off >>= 1)
        sum += __shfl_xor_sync(0xFFFFFFFFu, sum, off);
    if (lane == 0) red[wid] = sum;
    __syncthreads();
    sum = red[0];
#pragma unroll
    for (int w = 1; w < 8; w++) sum += red[w];

    float inv = 1.0f / sum;
#pragma unroll
    for (int i = 0; i < 8; i++) p[tid + i * 256] = v[i] * inv;
}

// ---------------------------------------------------------------------------
// Launch
// ---------------------------------------------------------------------------
extern "C" void kernel_launch(void* const* d_in, const int* in_sizes, int n_in,
                              void* d_out, int out_size)
{
    const float* x    = (const float*)d_in[0];
    const float* Wq   = (const float*)d_in[1];
    const float* Wk   = (const float*)d_in[2];
    const float* Wv   = (const float*)d_in[3];
    const float* hbar = (const float*)d_in[4];
    float* out = (float*)d_out;

    float *q, *k, *v, *sc, *tp;
    cudaGetSymbolAddress((void**)&q,  g_q);
    cudaGetSymbolAddress((void**)&k,  g_k);
    cudaGetSymbolAddress((void**)&v,  g_v);
    cudaGetSymbolAddress((void**)&sc, g_scores);
    cudaGetSymbolAddress((void**)&tp, g_temp);

    const int M = BB * TT;         // 16384
    dim3 blk(256);

    // 1) QKV projections: (16384 x 1024) = (16384 x 1024) * W^T
    dim3 gQKV(DD / BN, M / BM, 1); // (8, 128)
    gemm_nt<<<gQKV, blk>>>(x, Wq, q, M, DD, DD, 0, 0, 0, nullptr, 0);
    gemm_nt<<<gQKV, blk>>>(x, Wk, k, M, DD, DD, 0, 0, 0, nullptr, 0);
    gemm_nt<<<gQKV, blk>>>(x, Wv, v, M, DD, DD, 0, 0, 0, nullptr, 0);

    // 2) per-query temperature from ||q||
    qnorm_temp<<<M, 128>>>(q, hbar, tp);

    // 3) scores = (Q K^T) * temp[row], batched over B
    dim3 gS(TT / BN, TT / BM, BB); // (16, 16, 8)
    gemm_nt<<<gS, blk>>>(q, k, sc, TT, TT, DD,
                         (size_t)TT * DD, (size_t)TT * DD, (size_t)TT * TT,
                         tp, TT);

    // 4) softmax over last dim
    softmax_rows<<<M, 256>>>(sc);

    // 5) out = attn @ V, batched
    dim3 gO(DD / BN, TT / BM, BB); // (8, 16, 8)
    gemm_nn<<<gO, blk>>>(sc, v, out, TT, DD, TT,
                         (size_t)TT * TT, (size_t)TT * DD, (size_t)TT * DD);
}

// round 11
// speedup vs baseline: 2.1721x; 2.1721x over previous
#include <cuda_runtime.h>
#include <cuda_bf16.h>
#include <cstdint>
#include <math.h>

// ===========================================================================
// Problem constants
// ===========================================================================
#define BB 8
#define TT 2048
#define DD 1024
#define MQ (BB*TT)           // 16384 total query rows
#define MIN_TEMP 0.1f
#define MAX_TEMP 5.0f
#define EPS_T 1e-8f

typedef __nv_bfloat16  bf16;
typedef __nv_bfloat162 bf162;

// ===========================================================================
// Scratch (__device__ globals; no cudaMalloc allowed). 256B-aligned so all
// vectorized (float4 / bf162) and cp.async accesses are safe by construction.
// ===========================================================================
__device__ __align__(256) bf16  g_xhi[MQ*DD],  g_xlo[MQ*DD];
__device__ __align__(256) bf16  g_whi[3][DD*DD], g_wlo[3][DD*DD];
__device__ __align__(256) bf16  g_qhi[MQ*DD],  g_qlo[MQ*DD];
__device__ __align__(256) bf16  g_khi[MQ*DD],  g_klo[MQ*DD];
__device__ __align__(256) float g_v[MQ*DD];
__device__ __align__(256) bf16  g_vthi[MQ*DD], g_vtlo[MQ*DD];
__device__ __align__(256) float g_sc[(size_t)BB*TT*TT];
__device__ __align__(256) bf16  g_ahi[(size_t)BB*TT*TT];
__device__ __align__(256) bf16  g_alo[(size_t)BB*TT*TT];
__device__ __align__(256) float g_temp[MQ];

// ===========================================================================
// PTX helpers (sm_80-portable only: cp.async, mma.sync)
// ===========================================================================
__device__ __forceinline__ uint32_t smem_u32(const void* p) {
    uint32_t r;
    asm("{ .reg .u64 t; cvta.to.shared.u64 t, %1; cvt.u32.u64 %0, t; }"
        : "=r"(r) : "l"(p));
    return r;
}

__device__ __forceinline__ void cp_async16(uint32_t dst, const void* src) {
    asm volatile("cp.async.cg.shared.global [%0], [%1], 16;" :: "r"(dst), "l"(src));
}
__device__ __forceinline__ void cp_commit() {
    asm volatile("cp.async.commit_group;");
}
template<int N> __device__ __forceinline__ void cp_wait() {
    asm volatile("cp.async.wait_group %0;" :: "n"(N));
}

__device__ __forceinline__ void mma_bf16(float* c, const uint32_t* a,
                                         uint32_t b0, uint32_t b1) {
    asm volatile(
        "mma.sync.aligned.m16n8k16.row.col.f32.bf16.bf16.f32 "
        "{%0,%1,%2,%3}, {%4,%5,%6,%7}, {%8,%9}, {%0,%1,%2,%3};"
        : "+f"(c[0]), "+f"(c[1]), "+f"(c[2]), "+f"(c[3])
        : "r"(a[0]), "r"(a[1]), "r"(a[2]), "r"(a[3]), "r"(b0), "r"(b1));
}

// ===========================================================================
// HMMA GEMM: C[M,N] = sum over 3 split segments of A_seg[M,K] * B_seg[N,K]^T
//   A segments: {Ahi, Ahi, Alo};  B segments: {Bhi, Blo, Bhi}
//   Both operands K-major bf16. fp32 accumulate in registers.
//   mode 0: write fp32 (optional per-row temp scale);  mode 1: write bf16 split.
//
// Tile 128x128x32, 256 threads = 8 warps (2 M x 4 N), warp tile 64x32.
// Smem rows: 64 bytes (32 bf16). 16B-chunk swizzle: chunk' = chunk ^ ((row>>1)&3).
// Fragments loaded with plain per-thread LDS.32 in the exact mma.m16n8k16
// layout (no ldmatrix). Conflict-free under the swizzle.
// ===========================================================================
#define BM 128
#define BN 128
#define BK 32
#define NST 3
#define STAGE_A (BM*BK*2)            // 8 KB
#define STAGE_B (BN*BK*2)            // 8 KB
#define STAGE   (STAGE_A + STAGE_B)  // 16 KB
#define GEMM_SMEM (NST*STAGE)        // 48 KB (static)

// byte offset of (row, 16B-chunk) within a tile
__device__ __forceinline__ uint32_t swz_off(uint32_t row, uint32_t chunk) {
    return row * 64 + ((chunk ^ ((row >> 1) & 3)) << 4);
}

__device__ __forceinline__ void load_chunk(
    const char* Ap, const char* Bp, size_t ldbytes,
    uint32_t sA, uint32_t sB, int tid)
{
#pragma unroll
    for (int i = 0; i < 2; i++) {            // A: 128 rows x 4 chunks of 16B
        uint32_t id = tid + (i << 8);
        uint32_t row = id >> 2, ch = id & 3;
        cp_async16(sA + swz_off(row, ch), Ap + (size_t)row * ldbytes + ch * 16);
    }
#pragma unroll
    for (int i = 0; i < 2; i++) {            // B: 128 rows x 4 chunks of 16B
        uint32_t id = tid + (i << 8);
        uint32_t row = id >> 2, ch = id & 3;
        cp_async16(sB + swz_off(row, ch), Bp + (size_t)row * ldbytes + ch * 16);
    }
}

__global__ __launch_bounds__(256) void gemm_mma(
    const bf16* __restrict__ Ahi, const bf16* __restrict__ Alo,
    const bf16* __restrict__ Bhi, const bf16* __restrict__ Blo,
    int N, int K,
    size_t sA, size_t sB, size_t sC,
    float* __restrict__ outF,
    bf16* __restrict__ outHi, bf16* __restrict__ outLo,
    const float* __restrict__ temp, int mode)
{
    __shared__ __align__(1024) char smem[GEMM_SMEM];
    const uint32_t sb = smem_u32(smem);
    const int tid  = threadIdx.x;
    const int lane = tid & 31;
    const int warp = tid >> 5;
    const int wm   = warp >> 2;      // 0..1  (M)
    const int wn   = warp & 3;       // 0..3  (N)
    const int bz   = blockIdx.z;
    const int m0   = blockIdx.y * BM;
    const int n0   = blockIdx.x * BN;
    const int g    = lane >> 2;      // 0..7  fragment row-in-group
    const int tq   = lane & 3;       // 0..3  fragment col pair

    float acc[4][4][4];
#pragma unroll
    for (int i = 0; i < 4; i++)
#pragma unroll
        for (int j = 0; j < 4; j++)
#pragma unroll
            for (int r = 0; r < 4; r++) acc[i][j][r] = 0.0f;

    const int nkb = K / BK;
    const int NC  = 3 * nkb;
    const bf16* Aseg[3] = {Ahi, Ahi, Alo};
    const bf16* Bseg[3] = {Bhi, Blo, Bhi};
    const size_t aBase = (size_t)bz * sA + (size_t)m0 * K;
    const size_t bBase = (size_t)bz * sB + (size_t)n0 * K;
    const size_t ldb   = (size_t)K * 2;

    // prologue: stages 0..NST-2
#pragma unroll
    for (int p = 0; p < NST - 1; p++) {
        int seg = p / nkb, kb = (p - seg * nkb) * BK;
        load_chunk((const char*)(Aseg[seg] + aBase + kb),
                   (const char*)(Bseg[seg] + bBase + kb),
                   ldb, sb + p * STAGE, sb + p * STAGE + STAGE_A, tid);
        cp_commit();
    }

    for (int c = 0; c < NC; c++) {
        cp_wait<NST - 2>();
        __syncthreads();

        // early prefetch of chunk c+NST-1 into the buffer freed by chunk c-1
        // (all warps passed this iteration's barrier => chunk c-1 reads done)
        if (c + NST - 1 < NC) {
            int cc = c + NST - 1;
            int seg = cc / nkb, kb = (cc - seg * nkb) * BK;
            uint32_t st = sb + (cc % NST) * STAGE;
            load_chunk((const char*)(Aseg[seg] + aBase + kb),
                       (const char*)(Bseg[seg] + bBase + kb),
                       ldb, st, st + STAGE_A, tid);
        }
        cp_commit();

        const uint32_t offA = (uint32_t)((c % NST) * STAGE);
        const uint32_t offB = offA + STAGE_A;

#pragma unroll
        for (int s = 0; s < 2; s++) {            // two k16 steps per BK=32
            const uint32_t cLo = (uint32_t)(s * 2);
            const uint32_t cHi = cLo + 1;
            uint32_t a[4][4], bq[2][4];
#pragma unroll
            for (int mi = 0; mi < 4; mi++) {
                uint32_t r0 = (uint32_t)(wm * 64 + mi * 16 + g);
                uint32_t r1 = r0 + 8;
                a[mi][0] = *(const uint32_t*)(smem + offA + swz_off(r0, cLo) + tq * 4);
                a[mi][1] = *(const uint32_t*)(smem + offA + swz_off(r1, cLo) + tq * 4);
                a[mi][2] = *(const uint32_t*)(smem + offA + swz_off(r0, cHi) + tq * 4);
                a[mi][3] = *(const uint32_t*)(smem + offA + swz_off(r1, cHi) + tq * 4);
            }
#pragma unroll
            for (int nj = 0; nj < 2; nj++) {
                uint32_t r0 = (uint32_t)(wn * 32 + nj * 16 + g);
                uint32_t r1 = r0 + 8;
                bq[nj][0] = *(const uint32_t*)(smem + offB + swz_off(r0, cLo) + tq * 4);
                bq[nj][1] = *(const uint32_t*)(smem + offB + swz_off(r1, cLo) + tq * 4);
                bq[nj][2] = *(const uint32_t*)(smem + offB + swz_off(r0, cHi) + tq * 4);
                bq[nj][3] = *(const uint32_t*)(smem + offB + swz_off(r1, cHi) + tq * 4);
            }
#pragma unroll
            for (int mi = 0; mi < 4; mi++)
#pragma unroll
                for (int ni = 0; ni < 4; ni++)
                    mma_bf16(acc[mi][ni], a[mi],
                             bq[ni >> 1][ni & 1], bq[ni >> 1][(ni & 1) + 2]);
        }
    }

    // -------------------- epilogue (from registers) --------------------
#pragma unroll
    for (int mi = 0; mi < 4; mi++) {
        const int rowA = m0 + wm * 64 + mi * 16 + g;
        const int rowB = rowA + 8;
        float sa = 1.0f, sbt = 1.0f;
        if (temp != nullptr) {
            sa  = temp[bz * TT + rowA];
            sbt = temp[bz * TT + rowB];
        }
#pragma unroll
        for (int ni = 0; ni < 4; ni++) {
            const int col = n0 + wn * 32 + ni * 8 + tq * 2;
            if (mode == 0) {
                float2 o0 = make_float2(acc[mi][ni][0] * sa,  acc[mi][ni][1] * sa);
                float2 o1 = make_float2(acc[mi][ni][2] * sbt, acc[mi][ni][3] * sbt);
                *(float2*)(outF + (size_t)bz * sC + (size_t)rowA * N + col) = o0;
                *(float2*)(outF + (size_t)bz * sC + (size_t)rowB * N + col) = o1;
            } else {
                size_t offA2 = (size_t)bz * sC + (size_t)rowA * N + col;
                size_t offB2 = (size_t)bz * sC + (size_t)rowB * N + col;
                float v0 = acc[mi][ni][0], v1 = acc[mi][ni][1];
                float v2 = acc[mi][ni][2], v3 = acc[mi][ni][3];
                bf16 h0 = __float2bfloat16(v0), h1 = __float2bfloat16(v1);
                bf16 h2 = __float2bfloat16(v2), h3 = __float2bfloat16(v3);
                bf16 l0 = __float2bfloat16(v0 - __bfloat162float(h0));
                bf16 l1 = __float2bfloat16(v1 - __bfloat162float(h1));
                bf16 l2 = __float2bfloat16(v2 - __bfloat162float(h2));
                bf16 l3 = __float2bfloat16(v3 - __bfloat162float(h3));
                *(bf162*)(outHi + offA2) = __halves2bfloat162(h0, h1);
                *(bf162*)(outLo + offA2) = __halves2bfloat162(l0, l1);
                *(bf162*)(outHi + offB2) = __halves2bfloat162(h2, h3);
                *(bf162*)(outLo + offB2) = __halves2bfloat162(l2, l3);
            }
        }
    }
}

// ===========================================================================
// fp32 -> (hi, lo) bf16 split. 4 elems/thread.
// ===========================================================================
__global__ __launch_bounds__(256) void split_f32(
    const float* __restrict__ in, bf16* __restrict__ hi, bf16* __restrict__ lo)
{
    size_t i = ((size_t)blockIdx.x * 256 + threadIdx.x) * 4;
    float4 v = *(const float4*)(in + i);
    bf16 h0 = __float2bfloat16(v.x), h1 = __float2bfloat16(v.y);
    bf16 h2 = __float2bfloat16(v.z), h3 = __float2bfloat16(v.w);
    bf16 l0 = __float2bfloat16(v.x - __bfloat162float(h0));
    bf16 l1 = __float2bfloat16(v.y - __bfloat162float(h1));
    bf16 l2 = __float2bfloat16(v.z - __bfloat162float(h2));
    bf16 l3 = __float2bfloat16(v.w - __bfloat162float(h3));
    bf162* ph = (bf162*)(hi + i);
    bf162* pl = (bf162*)(lo + i);
    ph[0] = __halves2bfloat162(h0, h1);
    ph[1] = __halves2bfloat162(h2, h3);
    pl[0] = __halves2bfloat162(l0, l1);
    pl[1] = __halves2bfloat162(l2, l3);
}

// ===========================================================================
// temp = clip(hbar / (||q|| + eps)), q reconstructed from split
// ===========================================================================
__global__ __launch_bounds__(128) void qnorm_temp(
    const bf16* __restrict__ qhi, const bf16* __restrict__ qlo,
    const float* __restrict__ hbar, float* __restrict__ temp)
{
    const int row = blockIdx.x;
    const bf162* ph = (const bf162*)(qhi + (size_t)row * DD);
    const bf162* pl = (const bf162*)(qlo + (size_t)row * DD);
    float s = 0.0f;
    for (int i = threadIdx.x; i < DD / 2; i += 128) {
        float2 a = __bfloat1622float2(ph[i]);
        float2 b = __bfloat1622float2(pl[i]);
        float v0 = a.x + b.x, v1 = a.y + b.y;
        s = fmaf(v0, v0, fmaf(v1, v1, s));
    }
#pragma unroll
    for (int off = 16; off > 0; off >>= 1)
        s += __shfl_xor_sync(0xFFFFFFFFu, s, off);
    __shared__ float ws[4];
    int lane = threadIdx.x & 31, wid = threadIdx.x >> 5;
    if (lane == 0) ws[wid] = s;
    __syncthreads();
    if (threadIdx.x == 0) {
        float tot = ws[0] + ws[1] + ws[2] + ws[3];
        float t = hbar[0] / (sqrtf(tot) + EPS_T);
        temp[row] = fminf(fmaxf(t, MIN_TEMP), MAX_TEMP);
    }
}

// ===========================================================================
// Row softmax (2048 wide) reading fp32 scores, writing split bf16 attn.
// ===========================================================================
__global__ __launch_bounds__(256) void softmax_split(
    const float* __restrict__ sc, bf16* __restrict__ ahi, bf16* __restrict__ alo)
{
    const size_t base = (size_t)blockIdx.x * TT;
    const float* p = sc + base;
    const int tid = threadIdx.x;
    float v[8];
#pragma unroll
    for (int i = 0; i < 8; i++) v[i] = p[tid + i * 256];

    __shared__ float red[8];
    const int lane = tid & 31, wid = tid >> 5;

    float m = v[0];
#pragma unroll
    for (int i = 1; i < 8; i++) m = fmaxf(m, v[i]);
#pragma unroll
    for (int off = 16; off > 0; off >>= 1)
        m = fmaxf(m, __shfl_xor_sync(0xFFFFFFFFu, m, off));
    if (lane == 0) red[wid] = m;
    __syncthreads();
    m = red[0];
#pragma unroll
    for (int w = 1; w < 8; w++) m = fmaxf(m, red[w]);
    __syncthreads();

    float sum = 0.0f;
#pragma unroll
    for (int i = 0; i < 8; i++) {
        v[i] = expf(v[i] - m);
        sum += v[i];
    }
#pragma unroll
    for (int off = 16; off > 0; off >>= 1)
        sum += __shfl_xor_sync(0xFFFFFFFFu, sum, off);
    if (lane == 0) red[wid] = sum;
    __syncthreads();
    sum = red[0];
#pragma unroll
    for (int w = 1; w < 8; w++) sum += red[w];

    float inv = 1.0f / sum;
#pragma unroll
    for (int i = 0; i < 8; i++) {
        float pv = v[i] * inv;
        bf16 h = __float2bfloat16(pv);
        bf16 l = __float2bfloat16(pv - __bfloat162float(h));
        ahi[base + tid + i * 256] = h;
        alo[base + tid + i * 256] = l;
    }
}

// ===========================================================================
// Per-batch transpose + split: v[b][t][d] fp32 -> vT[b][d][t] bf16 hi/lo
// ===========================================================================
__global__ __launch_bounds__(256) void transpose_split(
    const float* __restrict__ v, bf16* __restrict__ thi, bf16* __restrict__ tlo)
{
    __shared__ float tile[32][33];
    const int b = blockIdx.z;
    const float* src = v + (size_t)b * TT * DD;
    bf16* dh = thi + (size_t)b * TT * DD;
    bf16* dl = tlo + (size_t)b * TT * DD;
    const int d0 = blockIdx.x * 32, t0 = blockIdx.y * 32;

    for (int r = threadIdx.y; r < 32; r += 8)
        tile[r][threadIdx.x] = src[(size_t)(t0 + r) * DD + d0 + threadIdx.x];
    __syncthreads();
    for (int r = threadIdx.y; r < 32; r += 8) {
        float val = tile[threadIdx.x][r];     // = v[t0+tx][d0+r]
        bf16 h = __float2bfloat16(val);
        bf16 l = __float2bfloat16(val - __bfloat162float(h));
        size_t o = (size_t)(d0 + r) * TT + t0 + threadIdx.x;
        dh[o] = h;
        dl[o] = l;
    }
}

// ===========================================================================
// Launch
// ===========================================================================
extern "C" void kernel_launch(void* const* d_in, const int* in_sizes, int n_in,
                              void* d_out, int out_size)
{
    const float* x    = (const float*)d_in[0];
    const float* Wq   = (const float*)d_in[1];
    const float* Wk   = (const float*)d_in[2];
    const float* Wv   = (const float*)d_in[3];
    const float* hbar = (const float*)d_in[4];
    float* out = (float*)d_out;

    bf16 *xhi, *xlo, *qhi, *qlo, *khi, *klo, *vthi, *vtlo, *ahi, *alo;
    bf16 *whi, *wlo;
    float *v, *sc, *tp;
    cudaGetSymbolAddress((void**)&xhi,  g_xhi);
    cudaGetSymbolAddress((void**)&xlo,  g_xlo);
    cudaGetSymbolAddress((void**)&whi,  g_whi);
    cudaGetSymbolAddress((void**)&wlo,  g_wlo);
    cudaGetSymbolAddress((void**)&qhi,  g_qhi);
    cudaGetSymbolAddress((void**)&qlo,  g_qlo);
    cudaGetSymbolAddress((void**)&khi,  g_khi);
    cudaGetSymbolAddress((void**)&klo,  g_klo);
    cudaGetSymbolAddress((void**)&v,    g_v);
    cudaGetSymbolAddress((void**)&vthi, g_vthi);
    cudaGetSymbolAddress((void**)&vtlo, g_vtlo);
    cudaGetSymbolAddress((void**)&sc,   g_sc);
    cudaGetSymbolAddress((void**)&ahi,  g_ahi);
    cudaGetSymbolAddress((void**)&alo,  g_alo);
    cudaGetSymbolAddress((void**)&tp,   g_temp);

    // 1) splits
    split_f32<<<MQ * DD / 1024, 256>>>(x, xhi, xlo);
    split_f32<<<DD * DD / 1024, 256>>>(Wq, whi + 0 * DD * DD, wlo + 0 * DD * DD);
    split_f32<<<DD * DD / 1024, 256>>>(Wk, whi + 1 * DD * DD, wlo + 1 * DD * DD);
    split_f32<<<DD * DD / 1024, 256>>>(Wv, whi + 2 * DD * DD, wlo + 2 * DD * DD);

    // 2) QKV projections: q,k -> split outputs; v -> fp32
    dim3 gP(DD / BN, MQ / BM, 1);   // (8, 128, 1)
    gemm_mma<<<gP, 256>>>(xhi, xlo, whi + 0 * DD * DD, wlo + 0 * DD * DD,
                          DD, DD, 0, 0, 0,
                          nullptr, qhi, qlo, nullptr, 1);
    gemm_mma<<<gP, 256>>>(xhi, xlo, whi + 1 * DD * DD, wlo + 1 * DD * DD,
                          DD, DD, 0, 0, 0,
                          nullptr, khi, klo, nullptr, 1);
    gemm_mma<<<gP, 256>>>(xhi, xlo, whi + 2 * DD * DD, wlo + 2 * DD * DD,
                          DD, DD, 0, 0, 0,
                          v, nullptr, nullptr, nullptr, 0);

    // 3) temperature + v transpose/split
    qnorm_temp<<<MQ, 128>>>(qhi, qlo, hbar, tp);
    transpose_split<<<dim3(DD / 32, TT / 32, BB), dim3(32, 8)>>>(v, vthi, vtlo);

    // 4) scores = (Q K^T) * temp, batched
    dim3 gS(TT / BN, TT / BM, BB);  // (16, 16, 8)
    gemm_mma<<<gS, 256>>>(qhi, qlo, khi, klo,
                          TT, DD,
                          (size_t)TT * DD, (size_t)TT * DD, (size_t)TT * TT,
                          sc, nullptr, nullptr, tp, 0);

    // 5) softmax -> split attn
    softmax_split<<<MQ, 256>>>(sc, ahi, alo);

    // 6) out = attn @ V, batched.
    //    FIX (R9, still untested — R9/R10 containers died pre-execution):
    //    vT per-batch stride is TT*DD, not TT*TT. The old value sent B reads
    //    up to ~22 MB past g_vthi for bz>=4 — random bytes as bf16 are NaN
    //    ~0.4% of the time, which propagated through mma to the output.
    dim3 gO(DD / BN, TT / BM, BB);  // (8, 16, 8)
    gemm_mma<<<gO, 256>>>(ahi, alo, vthi, vtlo,
                          DD, TT,
                          (size_t)TT * TT, (size_t)TT * DD, (size_t)TT * DD,
                          out, nullptr, nullptr, nullptr, 0);
}